// round 4
// baseline (speedup 1.0000x reference)
#include <cuda_runtime.h>
#include <cuda_bf16.h>
#include <stdint.h>

#define NN 20000      // nodes
#define NE 320000     // edges
#define DN 128
#define DE 128
#define DA 16
#define NH 256
#define NG 64
#define K1TOT 528

// ---------------- scratch ----------------
__device__ float g_nproj[NN * 8];
__device__ float g_eproj[NE * 2];     // attr-dot for upd, read
__device__ float g_logit[NE];
__device__ float g_w[NE];
__device__ float g_nmax[NN];
__device__ float g_nsum[NN];
__device__ float g_nodefeat[NN * DE];
__device__ uint32_t g_w1h[264 * 256], g_w1l[264 * 256];   // W1 bf16x2 split [kpair][n]
__device__ uint32_t g_w2h[128 * 128], g_w2l[128 * 128];   // W2 bf16x2 split [kpair][n]
__device__ float g_rlogit[NE];
__device__ float g_rw[NE];
__device__ float g_gmax[NG];
__device__ float g_gsum[NG];
__device__ float g_graphfeat[NG * DE];

// ---------------- helpers ----------------
__device__ __forceinline__ float dot4(float4 a, float4 b) {
    return fmaf(a.x, b.x, fmaf(a.y, b.y, fmaf(a.z, b.z, a.w * b.w)));
}

__device__ __forceinline__ float wred(float v) {
    v += __shfl_xor_sync(0xffffffffu, v, 16);
    v += __shfl_xor_sync(0xffffffffu, v, 8);
    v += __shfl_xor_sync(0xffffffffu, v, 4);
    v += __shfl_xor_sync(0xffffffffu, v, 2);
    v += __shfl_xor_sync(0xffffffffu, v, 1);
    return v;
}

__device__ __forceinline__ void atomicMaxF(float* addr, float v) {
    int* ia = (int*)addr;
    int old = __float_as_int(*addr);
    while (__int_as_float(old) < v) {
        int prev = atomicCAS(ia, old, __float_as_int(v));
        if (prev == old) break;
        old = prev;
    }
}

__device__ __forceinline__ uint32_t packhi(float f0, float f1) {
    __nv_bfloat162 h = __floats2bfloat162_rn(f0, f1);
    return *(uint32_t*)&h;
}
__device__ __forceinline__ uint32_t packlo(float f0, float f1, uint32_t hi) {
    __nv_bfloat162 h = *(__nv_bfloat162*)&hi;
    float l0 = f0 - __bfloat162float(h.x);
    float l1 = f1 - __bfloat162float(h.y);
    __nv_bfloat162 l = __floats2bfloat162_rn(l0, l1);
    return *(uint32_t*)&l;
}

__device__ __forceinline__ void mma16(float* c, const uint32_t* a, uint32_t b0, uint32_t b1) {
    asm volatile("mma.sync.aligned.m16n8k16.row.col.f32.bf16.bf16.f32 "
        "{%0,%1,%2,%3}, {%4,%5,%6,%7}, {%8,%9}, {%0,%1,%2,%3};"
        : "+f"(c[0]), "+f"(c[1]), "+f"(c[2]), "+f"(c[3])
        : "r"(a[0]), "r"(a[1]), "r"(a[2]), "r"(a[3]), "r"(b0), "r"(b1));
}

// ---------------- init scratch ----------------
__global__ void k_init() {
    int i = blockIdx.x * 256 + threadIdx.x;
    if (i < NN * DE) g_nodefeat[i] = 0.f;
    if (i < NN) { g_nmax[i] = -1e30f; g_nsum[i] = 0.f; }
    if (i < NG * DE) g_graphfeat[i] = 0.f;
    if (i < NG) { g_gmax[i] = -1e30f; g_gsum[i] = 0.f; }
}

// ---------------- one-time weight bf16 hi/lo split ----------------
__global__ void k_wsplit(const float* __restrict__ W1, const float* __restrict__ W2) {
    int i = blockIdx.x * 256 + threadIdx.x;
    if (i < 264 * 256) {
        int kp = i >> 8, n = i & 255;
        float f0 = W1[(2 * kp) * 256 + n], f1 = W1[(2 * kp + 1) * 256 + n];
        uint32_t h = packhi(f0, f1);
        g_w1h[i] = h; g_w1l[i] = packlo(f0, f1, h);
    }
    if (i < 128 * 128) {
        int kp = i >> 7, n = i & 127;
        float f0 = W2[(2 * kp) * 128 + n], f1 = W2[(2 * kp + 1) * 128 + n];
        uint32_t h = packhi(f0, f1);
        g_w2h[i] = h; g_w2l[i] = packlo(f0, f1, h);
    }
}

// ---------------- per-node scalar projections ----------------
__global__ void k_nodeproj(const float* __restrict__ x, const float* __restrict__ Wagg,
                           const float* __restrict__ Wupd, const float* __restrict__ Wread) {
    int warp = threadIdx.x >> 5, lane = threadIdx.x & 31;
    int n = blockIdx.x * 8 + warp;
    if (n >= NN) return;
    float4 xv = ((const float4*)x)[n * 32 + lane];
    const float4* wa = (const float4*)Wagg;
    const float4* wu = (const float4*)Wupd;
    const float4* wr = (const float4*)Wread;
    float s0 = dot4(xv, wa[lane]);
    float s1 = dot4(xv, wa[32 + lane]);
    float s2 = dot4(xv, wu[lane]);
    float s3 = dot4(xv, wu[32 + lane]);
    float s4 = dot4(xv, wr[lane]);
    float s5 = dot4(xv, wr[32 + lane]);
    s0 = wred(s0); s1 = wred(s1); s2 = wred(s2);
    s3 = wred(s3); s4 = wred(s4); s5 = wred(s5);
    if (lane == 0) {
        g_nproj[n * 8 + 0] = s0; g_nproj[n * 8 + 1] = s1;
        g_nproj[n * 8 + 2] = s2; g_nproj[n * 8 + 3] = s3;
        g_nproj[n * 8 + 4] = s4; g_nproj[n * 8 + 5] = s5;
    }
}

// ---------------- agg logits + segment max + attr projections ----------------
__global__ void k_agglogit(const float* __restrict__ hef, const float* __restrict__ attr,
                           const int* __restrict__ ei, const float* __restrict__ Wagg,
                           const float* __restrict__ bagg, const float* __restrict__ Wupd,
                           const float* __restrict__ Wread) {
    int warp = threadIdx.x >> 5, lane = threadIdx.x & 31;
    int e = blockIdx.x * 8 + warp;
    if (e >= NE) return;
    int r = ei[e], c = ei[NE + e];
    float4 h4 = ((const float4*)hef)[e * 32 + lane];
    float4 wh = *(const float4*)&Wagg[272 + lane * 4];
    float p = dot4(h4, wh);
    float pu = 0.f, pr = 0.f;
    if (lane < 4) {
        float4 a4 = ((const float4*)attr)[e * 4 + lane];
        p += dot4(a4, *(const float4*)&Wagg[256 + lane * 4]);
        pu = dot4(a4, *(const float4*)&Wupd[256 + lane * 4]);
        pr = dot4(a4, *(const float4*)&Wread[384 + lane * 4]);
    }
    p = wred(p); pu = wred(pu); pr = wred(pr);
    if (lane == 0) {
        float logit = p + g_nproj[r * 8 + 0] + g_nproj[c * 8 + 1] + bagg[0];
        g_logit[e] = logit;
        g_eproj[e * 2 + 0] = pu;
        g_eproj[e * 2 + 1] = pr;
        atomicMaxF(&g_nmax[c], logit);
    }
}

// ---------------- exp + segment sum ----------------
__global__ void k_expw(const int* __restrict__ ei) {
    int e = blockIdx.x * 256 + threadIdx.x;
    if (e >= NE) return;
    int c = ei[NE + e];
    float w = expf(g_logit[e] - g_nmax[c]);
    g_w[e] = w;
    atomicAdd(&g_nsum[c], w);
}

// ---------------- normalize + scatter (vector red) ----------------
__global__ void k_nscatter(const float* __restrict__ hef, const int* __restrict__ ei) {
    int warp = threadIdx.x >> 5, lane = threadIdx.x & 31;
    int e = blockIdx.x * 8 + warp;
    if (e >= NE) return;
    int c = ei[NE + e];
    float wn = g_w[e] / (g_nsum[c] + 1e-16f);
    float4 h4 = ((const float4*)hef)[e * 32 + lane];
    float* p = &g_nodefeat[c * 128 + lane * 4];
    asm volatile("red.global.add.v4.f32 [%0], {%1,%2,%3,%4};"
        :: "l"(p), "f"(wn * h4.x), "f"(wn * h4.y), "f"(wn * h4.z), "f"(wn * h4.w)
        : "memory");
}

// ==================== FUSED: GEMM1 + GEMM2 + gate + readout-logit ====================
// 256 threads, block = 128 edges. SMEM (u32 words):
//  AsH[16][136] @0   AsL @2176   BsH @4352   BsL @6528
//  HsH[64][136] @8704  HsL @17408
//  srol @26112  scol @26240  sred @26368 (256 f)  sg @26624 (128 f)
#define SM_WORDS 26752

__global__ void __launch_bounds__(256)
k_fused(const float* __restrict__ x, const float* __restrict__ attr,
        const float* __restrict__ hef, const int* __restrict__ ei,
        const int* __restrict__ batch,
        const float* __restrict__ b1, const float* __restrict__ b2,
        const float* __restrict__ Wupd, const float* __restrict__ bupd,
        const float* __restrict__ Wread, const float* __restrict__ bread,
        float* __restrict__ out) {
    extern __shared__ uint32_t sm_[];
    uint32_t (*AsH)[136] = (uint32_t(*)[136])(sm_ + 0);
    uint32_t (*AsL)[136] = (uint32_t(*)[136])(sm_ + 2176);
    uint32_t (*BsH)[136] = (uint32_t(*)[136])(sm_ + 4352);
    uint32_t (*BsL)[136] = (uint32_t(*)[136])(sm_ + 6528);
    uint32_t (*HsH)[136] = (uint32_t(*)[136])(sm_ + 8704);
    uint32_t (*HsL)[136] = (uint32_t(*)[136])(sm_ + 17408);
    int*   srol = (int*)(sm_ + 26112);
    int*   scol = (int*)(sm_ + 26240);
    float* sred = (float*)(sm_ + 26368);
    float* sg   = (float*)(sm_ + 26624);

    int t = threadIdx.x;
    int me0 = blockIdx.x * 128;
    if (t < 128) srol[t] = ei[me0 + t];
    else scol[t - 128] = ei[NE + me0 + t - 128];
    __syncthreads();

    int am = t >> 1, ak = (t & 1) * 8;
    int bkp = t >> 5, bn = (t & 31) * 4;
    int lane = t & 31, w = t >> 5;
    int wm = (w & 3) * 32, wn = (w >> 2) * 64;
    int grp = lane >> 2, quad = lane & 3;

    auto ldA = [&](int k) -> float4 {
        if (k < 128) return *(const float4*)&x[srol[am] * 128 + k];
        if (k < 256) return *(const float4*)&g_nodefeat[srol[am] * 128 + (k - 128)];
        if (k < 384) return *(const float4*)&x[scol[am] * 128 + (k - 256)];
        if (k < 512) return *(const float4*)&g_nodefeat[scol[am] * 128 + (k - 384)];
        return *(const float4*)&attr[(me0 + am) * 16 + (k - 512)];
    };

    auto stageA = [&](int buf, float4 a0, float4 a1) {
        int kp = (t & 1) * 4;
        float fa[8] = {a0.x, a0.y, a0.z, a0.w, a1.x, a1.y, a1.z, a1.w};
#pragma unroll
        for (int i = 0; i < 4; i++) {
            uint32_t h = packhi(fa[2 * i], fa[2 * i + 1]);
            AsH[buf * 8 + kp + i][am] = h;
            AsL[buf * 8 + kp + i][am] = packlo(fa[2 * i], fa[2 * i + 1], h);
        }
    };

    float acc2[2][8][4];
#pragma unroll
    for (int i = 0; i < 2; i++)
#pragma unroll
        for (int j = 0; j < 8; j++)
#pragma unroll
            for (int k = 0; k < 4; k++) acc2[i][j][k] = 0.f;

    for (int half = 0; half < 2; half++) {
        int hn0 = half * 128;
        float acc1[2][8][4];
#pragma unroll
        for (int i = 0; i < 2; i++)
#pragma unroll
            for (int j = 0; j < 8; j++)
#pragma unroll
                for (int k = 0; k < 4; k++) acc1[i][j][k] = 0.f;

        // ---- GEMM1 mainloop over K1TOT = 33 k16 tiles ----
        float4 a0 = ldA(ak), a1 = ldA(ak + 4);
        uint4 bh = *(const uint4*)&g_w1h[bkp * 256 + hn0 + bn];
        uint4 bl = *(const uint4*)&g_w1l[bkp * 256 + hn0 + bn];
        stageA(0, a0, a1);
        *(uint4*)&BsH[bkp][bn] = bh;
        *(uint4*)&BsL[bkp][bn] = bl;
        __syncthreads();

        for (int kt = 0; kt < 33; ++kt) {
            int cur = kt & 1;
            if (kt < 32) {
                int k0 = (kt + 1) * 16;
                a0 = ldA(k0 + ak); a1 = ldA(k0 + ak + 4);
                bh = *(const uint4*)&g_w1h[((kt + 1) * 8 + bkp) * 256 + hn0 + bn];
                bl = *(const uint4*)&g_w1l[((kt + 1) * 8 + bkp) * 256 + hn0 + bn];
            }
            uint32_t aH[2][4], aL[2][4];
#pragma unroll
            for (int mf = 0; mf < 2; mf++) {
                int r0 = wm + mf * 16 + grp, r1 = r0 + 8;
                aH[mf][0] = AsH[cur * 8 + quad][r0];
                aH[mf][1] = AsH[cur * 8 + quad][r1];
                aH[mf][2] = AsH[cur * 8 + quad + 4][r0];
                aH[mf][3] = AsH[cur * 8 + quad + 4][r1];
                aL[mf][0] = AsL[cur * 8 + quad][r0];
                aL[mf][1] = AsL[cur * 8 + quad][r1];
                aL[mf][2] = AsL[cur * 8 + quad + 4][r0];
                aL[mf][3] = AsL[cur * 8 + quad + 4][r1];
            }
#pragma unroll
            for (int nf = 0; nf < 8; nf++) {
                int nc = wn + nf * 8 + grp;
                uint32_t bH0 = BsH[cur * 8 + quad][nc], bH1 = BsH[cur * 8 + quad + 4][nc];
                uint32_t bL0 = BsL[cur * 8 + quad][nc], bL1 = BsL[cur * 8 + quad + 4][nc];
#pragma unroll
                for (int mf = 0; mf < 2; mf++) {
                    mma16(acc1[mf][nf], aH[mf], bH0, bH1);
                    mma16(acc1[mf][nf], aH[mf], bL0, bL1);
                    mma16(acc1[mf][nf], aL[mf], bH0, bH1);
                }
            }
            if (kt < 32) {
                int nb = cur ^ 1;
                stageA(nb, a0, a1);
                *(uint4*)&BsH[nb * 8 + bkp][bn] = bh;
                *(uint4*)&BsL[nb * 8 + bkp][bn] = bl;
            }
            __syncthreads();
        }

        // ---- convert hidden half (bias + relu) into HsH/HsL ----
#pragma unroll
        for (int mf = 0; mf < 2; mf++) {
            int r0 = wm + mf * 16 + grp;
#pragma unroll
            for (int nf = 0; nf < 8; nf++) {
                int c0 = wn + nf * 8 + quad * 2;
                float bb0 = b1[hn0 + c0], bb1 = b1[hn0 + c0 + 1];
                int kp = c0 >> 1;
                float v0 = fmaxf(acc1[mf][nf][0] + bb0, 0.f);
                float v1 = fmaxf(acc1[mf][nf][1] + bb1, 0.f);
                uint32_t hh = packhi(v0, v1);
                HsH[kp][r0] = hh;
                HsL[kp][r0] = packlo(v0, v1, hh);
                float v2 = fmaxf(acc1[mf][nf][2] + bb0, 0.f);
                float v3 = fmaxf(acc1[mf][nf][3] + bb1, 0.f);
                hh = packhi(v2, v3);
                HsH[kp][r0 + 8] = hh;
                HsL[kp][r0 + 8] = packlo(v2, v3, hh);
            }
        }
        __syncthreads();

        // ---- GEMM2 partial: acc2 += hiddenHalf @ W2[half] (8 k16 tiles) ----
        bh = *(const uint4*)&g_w2h[(half * 64 + bkp) * 128 + bn];
        bl = *(const uint4*)&g_w2l[(half * 64 + bkp) * 128 + bn];
        *(uint4*)&BsH[bkp][bn] = bh;
        *(uint4*)&BsL[bkp][bn] = bl;
        __syncthreads();

        for (int kt = 0; kt < 8; ++kt) {
            int cur = kt & 1;
            if (kt < 7) {
                bh = *(const uint4*)&g_w2h[(half * 64 + (kt + 1) * 8 + bkp) * 128 + bn];
                bl = *(const uint4*)&g_w2l[(half * 64 + (kt + 1) * 8 + bkp) * 128 + bn];
            }
            uint32_t aH[2][4], aL[2][4];
#pragma unroll
            for (int mf = 0; mf < 2; mf++) {
                int r0 = wm + mf * 16 + grp, r1 = r0 + 8;
                aH[mf][0] = HsH[kt * 8 + quad][r0];
                aH[mf][1] = HsH[kt * 8 + quad][r1];
                aH[mf][2] = HsH[kt * 8 + quad + 4][r0];
                aH[mf][3] = HsH[kt * 8 + quad + 4][r1];
                aL[mf][0] = HsL[kt * 8 + quad][r0];
                aL[mf][1] = HsL[kt * 8 + quad][r1];
                aL[mf][2] = HsL[kt * 8 + quad + 4][r0];
                aL[mf][3] = HsL[kt * 8 + quad + 4][r1];
            }
#pragma unroll
            for (int nf = 0; nf < 8; nf++) {
                int nc = wn + nf * 8 + grp;
                uint32_t bH0 = BsH[cur * 8 + quad][nc], bH1 = BsH[cur * 8 + quad + 4][nc];
                uint32_t bL0 = BsL[cur * 8 + quad][nc], bL1 = BsL[cur * 8 + quad + 4][nc];
#pragma unroll
                for (int mf = 0; mf < 2; mf++) {
                    mma16(acc2[mf][nf], aH[mf], bH0, bH1);
                    mma16(acc2[mf][nf], aH[mf], bL0, bL1);
                    mma16(acc2[mf][nf], aL[mf], bH0, bH1);
                }
            }
            if (kt < 7) {
                int nb = cur ^ 1;
                *(uint4*)&BsH[nb * 8 + bkp][bn] = bh;
                *(uint4*)&BsL[nb * 8 + bkp][bn] = bl;
            }
            __syncthreads();
        }
    }

    // ---- add b2: acc2 now = cand (before bias) ----
#pragma unroll
    for (int mf = 0; mf < 2; mf++)
#pragma unroll
        for (int nf = 0; nf < 8; nf++) {
            int c0 = wn + nf * 8 + quad * 2;
            float bb0 = b2[c0], bb1 = b2[c0 + 1];
            acc2[mf][nf][0] += bb0; acc2[mf][nf][1] += bb1;
            acc2[mf][nf][2] += bb0; acc2[mf][nf][3] += bb1;
        }

    // ---- epilogue pass 1: gate logit dot (cand + hef parts) ----
    float s0 = 0.f, s1 = 0.f, s2 = 0.f, s3 = 0.f;
#pragma unroll
    for (int mf = 0; mf < 2; mf++) {
        int r0 = wm + mf * 16 + grp;
#pragma unroll
        for (int nf = 0; nf < 8; nf++) {
            int c = wn + nf * 8 + quad * 2;
            float2 wc = *(const float2*)&Wupd[400 + c];
            float2 whv = *(const float2*)&Wupd[272 + c];
            float2 h0 = *(const float2*)&hef[(me0 + r0) * 128 + c];
            float2 h1 = *(const float2*)&hef[(me0 + r0 + 8) * 128 + c];
            float p0 = acc2[mf][nf][0] * wc.x + acc2[mf][nf][1] * wc.y + h0.x * whv.x + h0.y * whv.y;
            float p1 = acc2[mf][nf][2] * wc.x + acc2[mf][nf][3] * wc.y + h1.x * whv.x + h1.y * whv.y;
            if (mf == 0) { s0 += p0; s1 += p1; } else { s2 += p0; s3 += p1; }
        }
    }
    s0 += __shfl_xor_sync(0xffffffffu, s0, 1); s0 += __shfl_xor_sync(0xffffffffu, s0, 2);
    s1 += __shfl_xor_sync(0xffffffffu, s1, 1); s1 += __shfl_xor_sync(0xffffffffu, s1, 2);
    s2 += __shfl_xor_sync(0xffffffffu, s2, 1); s2 += __shfl_xor_sync(0xffffffffu, s2, 2);
    s3 += __shfl_xor_sync(0xffffffffu, s3, 1); s3 += __shfl_xor_sync(0xffffffffu, s3, 2);
    if (quad == 0) {
        int wc2 = w >> 2;
        sred[(wm + grp) * 2 + wc2] = s0;
        sred[(wm + 8 + grp) * 2 + wc2] = s1;
        sred[(wm + 16 + grp) * 2 + wc2] = s2;
        sred[(wm + 24 + grp) * 2 + wc2] = s3;
    }
    __syncthreads();
    if (t < 128) {
        int e = me0 + t, r = srol[t], c = scol[t];
        float tot = sred[t * 2] + sred[t * 2 + 1];
        float gv = tot + g_eproj[e * 2] + g_nproj[r * 8 + 2] + g_nproj[c * 8 + 3] + bupd[0];
        sg[t] = 1.f / (1.f + expf(-gv));
    }
    __syncthreads();

    // ---- epilogue pass 2: ef = g*cand + (1-g)*hef, write out, readout dot ----
    s0 = s1 = s2 = s3 = 0.f;
#pragma unroll
    for (int mf = 0; mf < 2; mf++) {
        int r0 = wm + mf * 16 + grp;
        float g0 = sg[r0], g1 = sg[r0 + 8];
#pragma unroll
        for (int nf = 0; nf < 8; nf++) {
            int c = wn + nf * 8 + quad * 2;
            float2 h0 = *(const float2*)&hef[(me0 + r0) * 128 + c];
            float2 h1 = *(const float2*)&hef[(me0 + r0 + 8) * 128 + c];
            float2 e0, e1;
            e0.x = fmaf(g0, acc2[mf][nf][0] - h0.x, h0.x);
            e0.y = fmaf(g0, acc2[mf][nf][1] - h0.y, h0.y);
            e1.x = fmaf(g1, acc2[mf][nf][2] - h1.x, h1.x);
            e1.y = fmaf(g1, acc2[mf][nf][3] - h1.y, h1.y);
            *(float2*)&out[(me0 + r0) * 128 + c] = e0;
            *(float2*)&out[(me0 + r0 + 8) * 128 + c] = e1;
            float2 wr = *(const float2*)&Wread[256 + c];
            float p0 = e0.x * wr.x + e0.y * wr.y;
            float p1 = e1.x * wr.x + e1.y * wr.y;
            if (mf == 0) { s0 += p0; s1 += p1; } else { s2 += p0; s3 += p1; }
        }
    }
    s0 += __shfl_xor_sync(0xffffffffu, s0, 1); s0 += __shfl_xor_sync(0xffffffffu, s0, 2);
    s1 += __shfl_xor_sync(0xffffffffu, s1, 1); s1 += __shfl_xor_sync(0xffffffffu, s1, 2);
    s2 += __shfl_xor_sync(0xffffffffu, s2, 1); s2 += __shfl_xor_sync(0xffffffffu, s2, 2);
    s3 += __shfl_xor_sync(0xffffffffu, s3, 1); s3 += __shfl_xor_sync(0xffffffffu, s3, 2);
    if (quad == 0) {
        int wc2 = w >> 2;
        sred[(wm + grp) * 2 + wc2] = s0;
        sred[(wm + 8 + grp) * 2 + wc2] = s1;
        sred[(wm + 16 + grp) * 2 + wc2] = s2;
        sred[(wm + 24 + grp) * 2 + wc2] = s3;
    }
    __syncthreads();
    if (t < 128) {
        int e = me0 + t, r = srol[t], c = scol[t];
        float tot = sred[t * 2] + sred[t * 2 + 1];
        float rl = tot + g_eproj[e * 2 + 1] + g_nproj[r * 8 + 4] + g_nproj[c * 8 + 5] + bread[0];
        g_rlogit[e] = rl;
        atomicMaxF(&g_gmax[batch[r]], rl);
    }
}

// ---------------- readout exp + segment sum ----------------
__global__ void k_rexp(const int* __restrict__ ei, const int* __restrict__ batch) {
    __shared__ float ss[NG];
    int t = threadIdx.x;
    if (t < NG) ss[t] = 0.f;
    __syncthreads();
    int e = blockIdx.x * 256 + t;
    if (e < NE) {
        int gi = batch[ei[e]];
        float rw = expf(g_rlogit[e] - g_gmax[gi]);
        g_rw[e] = rw;
        atomicAdd(&ss[gi], rw);
    }
    __syncthreads();
    if (t < NG && ss[t] != 0.f) atomicAdd(&g_gsum[t], ss[t]);
}

// ---------------- readout scatter ----------------
__global__ void k_rscatter(const int* __restrict__ ei, const int* __restrict__ batch,
                           const float* __restrict__ out) {
    __shared__ float sacc[NG * DE];
    int t = threadIdx.x;
    for (int i = t; i < NG * DE; i += 256) sacc[i] = 0.f;
    __syncthreads();
    int warp = t >> 5, lane = t & 31;
    for (int e = blockIdx.x * 8 + warp; e < NE; e += gridDim.x * 8) {
        int gi = batch[ei[e]];
        float rn = g_rw[e] / (g_gsum[gi] + 1e-16f);
        float4 ef = ((const float4*)out)[e * 32 + lane];
        float* p = &sacc[gi * 128 + lane * 4];
        atomicAdd(p + 0, rn * ef.x);
        atomicAdd(p + 1, rn * ef.y);
        atomicAdd(p + 2, rn * ef.z);
        atomicAdd(p + 3, rn * ef.w);
    }
    __syncthreads();
    for (int i = t; i < NG * DE; i += 256)
        if (sacc[i] != 0.f) atomicAdd(&g_graphfeat[i], sacc[i]);
}

// ---------------- confidence ----------------
__global__ void k_conf(const float* __restrict__ Wscore, const float* __restrict__ bscore,
                       float* __restrict__ out) {
    int g = blockIdx.x, t = threadIdx.x;
    float v = g_graphfeat[g * 128 + t] * Wscore[t];
    v = wred(v);
    __shared__ float sm[4];
    if ((t & 31) == 0) sm[t >> 5] = v;
    __syncthreads();
    if (t == 0) {
        float s = sm[0] + sm[1] + sm[2] + sm[3] + bscore[0];
        out[(size_t)NE * DE + g] = 1.f / (1.f + expf(-s));
    }
}

// ---------------- launch ----------------
extern "C" void kernel_launch(void* const* d_in, const int* in_sizes, int n_in,
                              void* d_out, int out_size) {
    const float* x      = (const float*)d_in[0];
    const float* hef    = (const float*)d_in[1];
    const float* attr   = (const float*)d_in[2];
    const int*   ei     = (const int*)d_in[3];
    const int*   batch  = (const int*)d_in[4];
    const float* Wagg   = (const float*)d_in[6];
    const float* bagg   = (const float*)d_in[7];
    const float* W1     = (const float*)d_in[8];
    const float* b1     = (const float*)d_in[9];
    const float* W2     = (const float*)d_in[10];
    const float* b2     = (const float*)d_in[11];
    const float* Wupd   = (const float*)d_in[12];
    const float* bupd   = (const float*)d_in[13];
    const float* Wread  = (const float*)d_in[14];
    const float* bread  = (const float*)d_in[15];
    const float* Wscore = (const float*)d_in[16];
    const float* bscore = (const float*)d_in[17];
    float* out = (float*)d_out;

    static bool attr_set = false;
    if (!attr_set) {
        cudaFuncSetAttribute(k_fused, cudaFuncAttributeMaxDynamicSharedMemorySize,
                             SM_WORDS * 4);
        attr_set = true;
    }

    k_init<<<(NN * DE + 255) / 256, 256>>>();
    k_wsplit<<<(264 * 256 + 255) / 256, 256>>>(W1, W2);
    k_nodeproj<<<(NN + 7) / 8, 256>>>(x, Wagg, Wupd, Wread);
    k_agglogit<<<NE / 8, 256>>>(hef, attr, ei, Wagg, bagg, Wupd, Wread);
    k_expw<<<NE / 256, 256>>>(ei);
    k_nscatter<<<NE / 8, 256>>>(hef, ei);
    k_fused<<<NE / 128, 256, SM_WORDS * 4>>>(x, attr, hef, ei, batch, b1, b2,
                                             Wupd, bupd, Wread, bread, out);
    k_rexp<<<NE / 256, 256>>>(ei, batch);
    k_rscatter<<<296, 256>>>(ei, batch, out);
    k_conf<<<NG, 128>>>(Wscore, bscore, out);
}

// round 5
// speedup vs baseline: 1.2238x; 1.2238x over previous
#include <cuda_runtime.h>
#include <cuda_bf16.h>
#include <stdint.h>

#define NN 20000
#define NE 320000
#define DN 128
#define DE 128
#define DA 16
#define NH 256
#define NG 64
#define K1TOT 528
#define ST 12              // smem row stride in u32 words (8 used + 4 pad)

// ---------------- scratch ----------------
__device__ float g_nproj[NN * 8];
__device__ float g_logit[NE];
__device__ float g_w[NE];
__device__ float g_nmax[NN];
__device__ float g_nsum[NN];
__device__ float g_nodefeat[NN * DE];
__device__ uint32_t g_w1h[256 * 264], g_w1l[256 * 264];   // W1 split, [n][kpair]
__device__ uint32_t g_w2h[128 * 128], g_w2l[128 * 128];   // W2 split, [n][kpair]
__device__ uint32_t g_hh[40960000], g_hl[40960000];       // hidden packed [m][kpair]
__device__ float g_cand[40960000];
__device__ float g_rlogit[NE];
__device__ float g_rw[NE];
__device__ float g_gmax[NG];
__device__ float g_gsum[NG];
__device__ float g_graphfeat[NG * DE];

// ---------------- helpers ----------------
__device__ __forceinline__ float dot4(float4 a, float4 b) {
    return fmaf(a.x, b.x, fmaf(a.y, b.y, fmaf(a.z, b.z, a.w * b.w)));
}

__device__ __forceinline__ float wred(float v) {
    v += __shfl_xor_sync(0xffffffffu, v, 16);
    v += __shfl_xor_sync(0xffffffffu, v, 8);
    v += __shfl_xor_sync(0xffffffffu, v, 4);
    v += __shfl_xor_sync(0xffffffffu, v, 2);
    v += __shfl_xor_sync(0xffffffffu, v, 1);
    return v;
}

__device__ __forceinline__ void atomicMaxF(float* addr, float v) {
    int* ia = (int*)addr;
    int old = __float_as_int(*addr);
    while (__int_as_float(old) < v) {
        int prev = atomicCAS(ia, old, __float_as_int(v));
        if (prev == old) break;
        old = prev;
    }
}

__device__ __forceinline__ uint32_t packhi(float f0, float f1) {
    __nv_bfloat162 h = __floats2bfloat162_rn(f0, f1);
    return *(uint32_t*)&h;
}
__device__ __forceinline__ uint32_t packlo(float f0, float f1, uint32_t hi) {
    __nv_bfloat162 h = *(__nv_bfloat162*)&hi;
    float l0 = f0 - __bfloat162float(h.x);
    float l1 = f1 - __bfloat162float(h.y);
    __nv_bfloat162 l = __floats2bfloat162_rn(l0, l1);
    return *(uint32_t*)&l;
}

__device__ __forceinline__ void mma16(float* c, const uint32_t* a, uint32_t b0, uint32_t b1) {
    asm volatile("mma.sync.aligned.m16n8k16.row.col.f32.bf16.bf16.f32 "
        "{%0,%1,%2,%3}, {%4,%5,%6,%7}, {%8,%9}, {%0,%1,%2,%3};"
        : "+f"(c[0]), "+f"(c[1]), "+f"(c[2]), "+f"(c[3])
        : "r"(a[0]), "r"(a[1]), "r"(a[2]), "r"(a[3]), "r"(b0), "r"(b1));
}

__device__ __forceinline__ void ldsm4(uint32_t* r, uint32_t addr) {
    asm volatile("ldmatrix.sync.aligned.m8n8.x4.shared.b16 {%0,%1,%2,%3}, [%4];"
        : "=r"(r[0]), "=r"(r[1]), "=r"(r[2]), "=r"(r[3]) : "r"(addr));
}

// ---------------- init ----------------
__global__ void k_init() {
    int i = blockIdx.x * 256 + threadIdx.x;
    if (i < NN * DE) g_nodefeat[i] = 0.f;
    if (i < NN) { g_nmax[i] = -1e30f; g_nsum[i] = 0.f; }
    if (i < NG * DE) g_graphfeat[i] = 0.f;
    if (i < NG) { g_gmax[i] = -1e30f; g_gsum[i] = 0.f; }
}

// ---------------- one-time weight bf16 hi/lo split (transposed [n][kp]) ----------------
__global__ void k_wsplit(const float* __restrict__ W1, const float* __restrict__ W2) {
    int i = blockIdx.x * 256 + threadIdx.x;
    if (i < 256 * 264) {
        int n = i / 264, kp = i % 264;
        float f0 = W1[(2 * kp) * 256 + n], f1 = W1[(2 * kp + 1) * 256 + n];
        uint32_t h = packhi(f0, f1);
        g_w1h[i] = h; g_w1l[i] = packlo(f0, f1, h);
    }
    if (i < 128 * 128) {
        int n = i >> 7, kp = i & 127;
        float f0 = W2[(2 * kp) * 128 + n], f1 = W2[(2 * kp + 1) * 128 + n];
        uint32_t h = packhi(f0, f1);
        g_w2h[i] = h; g_w2l[i] = packlo(f0, f1, h);
    }
}

// ---------------- per-node scalar projections ----------------
__global__ void k_nodeproj(const float* __restrict__ x, const float* __restrict__ Wagg,
                           const float* __restrict__ Wupd, const float* __restrict__ Wread) {
    int warp = threadIdx.x >> 5, lane = threadIdx.x & 31;
    int n = blockIdx.x * 8 + warp;
    if (n >= NN) return;
    float4 xv = ((const float4*)x)[n * 32 + lane];
    const float4* wa = (const float4*)Wagg;
    const float4* wu = (const float4*)Wupd;
    const float4* wr = (const float4*)Wread;
    float s0 = dot4(xv, wa[lane]);
    float s1 = dot4(xv, wa[32 + lane]);
    float s2 = dot4(xv, wu[lane]);
    float s3 = dot4(xv, wu[32 + lane]);
    float s4 = dot4(xv, wr[lane]);
    float s5 = dot4(xv, wr[32 + lane]);
    s0 = wred(s0); s1 = wred(s1); s2 = wred(s2);
    s3 = wred(s3); s4 = wred(s4); s5 = wred(s5);
    if (lane == 0) {
        g_nproj[n * 8 + 0] = s0; g_nproj[n * 8 + 1] = s1;
        g_nproj[n * 8 + 2] = s2; g_nproj[n * 8 + 3] = s3;
        g_nproj[n * 8 + 4] = s4; g_nproj[n * 8 + 5] = s5;
    }
}

// ---------------- agg logits + segment max ----------------
__global__ void k_agglogit(const float* __restrict__ hef, const float* __restrict__ attr,
                           const int* __restrict__ ei, const float* __restrict__ Wagg,
                           const float* __restrict__ bagg) {
    int warp = threadIdx.x >> 5, lane = threadIdx.x & 31;
    int e = blockIdx.x * 8 + warp;
    if (e >= NE) return;
    int r = ei[e], c = ei[NE + e];
    float4 h4 = ((const float4*)hef)[e * 32 + lane];
    float4 wh = *(const float4*)&Wagg[272 + lane * 4];
    float p = dot4(h4, wh);
    if (lane < 4) {
        float4 a4 = ((const float4*)attr)[e * 4 + lane];
        float4 wa = *(const float4*)&Wagg[256 + lane * 4];
        p += dot4(a4, wa);
    }
    p = wred(p);
    if (lane == 0) {
        float logit = p + g_nproj[r * 8 + 0] + g_nproj[c * 8 + 1] + bagg[0];
        g_logit[e] = logit;
        atomicMaxF(&g_nmax[c], logit);
    }
}

// ---------------- exp + segment sum ----------------
__global__ void k_expw(const int* __restrict__ ei) {
    int e = blockIdx.x * 256 + threadIdx.x;
    if (e >= NE) return;
    int c = ei[NE + e];
    float w = expf(g_logit[e] - g_nmax[c]);
    g_w[e] = w;
    atomicAdd(&g_nsum[c], w);
}

// ---------------- normalize + scatter (vector red) ----------------
__global__ void k_nscatter(const float* __restrict__ hef, const int* __restrict__ ei) {
    int warp = threadIdx.x >> 5, lane = threadIdx.x & 31;
    int e = blockIdx.x * 8 + warp;
    if (e >= NE) return;
    int c = ei[NE + e];
    float wn = g_w[e] / (g_nsum[c] + 1e-16f);
    float4 h4 = ((const float4*)hef)[e * 32 + lane];
    float* p = &g_nodefeat[c * 128 + lane * 4];
    asm volatile("red.global.add.v4.f32 [%0], {%1,%2,%3,%4};"
        :: "l"(p), "f"(wn * h4.x), "f"(wn * h4.y), "f"(wn * h4.z), "f"(wn * h4.w)
        : "memory");
}

// ==================== GEMM1 (ldmatrix + pre-split B): hidden packed out ====================
// smem words: AsH[2][128][ST] @0, AsL @3072, BsH @6144, BsL @9216, srol @12288, scol @12416
#define G1_WORDS 12544

__global__ void __launch_bounds__(256, 2)
k_gemm1(const float* __restrict__ x, const float* __restrict__ attr,
        const int* __restrict__ ei, const float* __restrict__ b1) {
    extern __shared__ uint32_t sm_[];
    uint32_t* AsH = sm_;
    uint32_t* AsL = sm_ + 3072;
    uint32_t* BsH = sm_ + 6144;
    uint32_t* BsL = sm_ + 9216;
    int* srol = (int*)(sm_ + 12288);
    int* scol = srol + 128;

    int t = threadIdx.x;
    int me0 = blockIdx.x * 128, hn0 = blockIdx.y * 128;
    if (t < 128) srol[t] = ei[me0 + t];
    else scol[t - 128] = ei[NE + me0 + t - 128];
    __syncthreads();

    int am = t >> 1, ak = (t & 1) * 8, sw = (t & 1) * 4;
    int lane = t & 31, w = t >> 5;
    int wm = (w & 3) * 32, wn = (w >> 2) * 64;
    int grp = lane >> 2, quad = lane & 3;

    uint32_t smb = (uint32_t)__cvta_generic_to_shared(sm_);
    // ldmatrix read addresses (buffer 0)
    int arow = wm + (lane & 15);
    uint32_t rA = smb + arow * (ST * 4) + ((lane & 16) ? 16 : 0);
    int brow = wn + (lane & 7) + ((lane & 16) ? 8 : 0);
    uint32_t rB = smb + 6144 * 4 + brow * (ST * 4) + ((lane & 8) ? 16 : 0);
    const uint32_t BUFB = 1536 * 4;   // bytes per buffer
    const uint32_t LOFF = 3072 * 4;   // H -> L byte offset

    auto ldA = [&](int k) -> float4 {
        if (k < 128) return *(const float4*)&x[srol[am] * 128 + k];
        if (k < 256) return *(const float4*)&g_nodefeat[srol[am] * 128 + (k - 128)];
        if (k < 384) return *(const float4*)&x[scol[am] * 128 + (k - 256)];
        if (k < 512) return *(const float4*)&g_nodefeat[scol[am] * 128 + (k - 384)];
        return *(const float4*)&attr[(me0 + am) * 16 + (k - 512)];
    };

    auto stage = [&](int buf, float4 a0, float4 a1, uint4 bh, uint4 bl) {
        float fa[8] = {a0.x, a0.y, a0.z, a0.w, a1.x, a1.y, a1.z, a1.w};
        uint4 h4, l4;
#pragma unroll
        for (int i = 0; i < 4; i++) {
            uint32_t h = packhi(fa[2 * i], fa[2 * i + 1]);
            ((uint32_t*)&h4)[i] = h;
            ((uint32_t*)&l4)[i] = packlo(fa[2 * i], fa[2 * i + 1], h);
        }
        int o = buf * 1536 + am * ST + sw;
        *(uint4*)&AsH[o] = h4;
        *(uint4*)&AsL[o] = l4;
        *(uint4*)&BsH[o] = bh;
        *(uint4*)&BsL[o] = bl;
    };

    float4 a0 = ldA(ak), a1 = ldA(ak + 4);
    uint4 bh = *(const uint4*)&g_w1h[(size_t)(hn0 + am) * 264 + sw];
    uint4 bl = *(const uint4*)&g_w1l[(size_t)(hn0 + am) * 264 + sw];
    stage(0, a0, a1, bh, bl);
    __syncthreads();

    float acc[2][8][4];
#pragma unroll
    for (int i = 0; i < 2; i++)
#pragma unroll
        for (int j = 0; j < 8; j++)
#pragma unroll
            for (int k = 0; k < 4; k++) acc[i][j][k] = 0.f;

    const int KT = K1TOT / 16;  // 33
    for (int kt = 0; kt < KT; ++kt) {
        int cur = kt & 1;
        if (kt < KT - 1) {
            int k0 = (kt + 1) * 16;
            a0 = ldA(k0 + ak); a1 = ldA(k0 + ak + 4);
            bh = *(const uint4*)&g_w1h[(size_t)(hn0 + am) * 264 + (kt + 1) * 8 + sw];
            bl = *(const uint4*)&g_w1l[(size_t)(hn0 + am) * 264 + (kt + 1) * 8 + sw];
        }
        uint32_t aH[2][4], aL[2][4];
#pragma unroll
        for (int mf = 0; mf < 2; mf++) {
            uint32_t ad = rA + cur * BUFB + mf * (16 * ST * 4);
            ldsm4(aH[mf], ad);
            ldsm4(aL[mf], ad + LOFF);
        }
#pragma unroll
        for (int j = 0; j < 4; j++) {
            uint32_t bH[4], bL[4];
            uint32_t bd = rB + cur * BUFB + j * (16 * ST * 4);
            ldsm4(bH, bd);
            ldsm4(bL, bd + LOFF);
#pragma unroll
            for (int mf = 0; mf < 2; mf++) {
                mma16(acc[mf][2 * j],     aH[mf], bH[0], bH[1]);
                mma16(acc[mf][2 * j],     aH[mf], bL[0], bL[1]);
                mma16(acc[mf][2 * j],     aL[mf], bH[0], bH[1]);
                mma16(acc[mf][2 * j + 1], aH[mf], bH[2], bH[3]);
                mma16(acc[mf][2 * j + 1], aH[mf], bL[2], bL[3]);
                mma16(acc[mf][2 * j + 1], aL[mf], bH[2], bH[3]);
            }
        }
        if (kt < KT - 1) stage(cur ^ 1, a0, a1, bh, bl);
        __syncthreads();
    }

    // epilogue: bias + relu, pack hi/lo, write g_hh/g_hl
#pragma unroll
    for (int mf = 0; mf < 2; mf++) {
        int m = me0 + wm + mf * 16 + grp;
#pragma unroll
        for (int nf = 0; nf < 8; nf++) {
            int c0 = hn0 + wn + nf * 8 + quad * 2;
            float bb0 = b1[c0], bb1 = b1[c0 + 1];
            int kp = c0 >> 1;
            float v0 = fmaxf(acc[mf][nf][0] + bb0, 0.f);
            float v1 = fmaxf(acc[mf][nf][1] + bb1, 0.f);
            uint32_t h = packhi(v0, v1);
            g_hh[(size_t)m * 128 + kp] = h;
            g_hl[(size_t)m * 128 + kp] = packlo(v0, v1, h);
            float v2 = fmaxf(acc[mf][nf][2] + bb0, 0.f);
            float v3 = fmaxf(acc[mf][nf][3] + bb1, 0.f);
            h = packhi(v2, v3);
            g_hh[(size_t)(m + 8) * 128 + kp] = h;
            g_hl[(size_t)(m + 8) * 128 + kp] = packlo(v2, v3, h);
        }
    }
}

// ==================== GEMM2 (ldmatrix, all operands pre-split): cand ====================
#define G2_WORDS 12288

__global__ void __launch_bounds__(256, 2)
k_gemm2(const float* __restrict__ b2) {
    extern __shared__ uint32_t sm_[];
    uint32_t* AsH = sm_;
    uint32_t* AsL = sm_ + 3072;
    uint32_t* BsH = sm_ + 6144;
    uint32_t* BsL = sm_ + 9216;

    int t = threadIdx.x;
    int me0 = blockIdx.x * 128;
    int am = t >> 1, sw = (t & 1) * 4;
    int lane = t & 31, w = t >> 5;
    int wm = (w & 3) * 32, wn = (w >> 2) * 64;
    int grp = lane >> 2, quad = lane & 3;

    uint32_t smb = (uint32_t)__cvta_generic_to_shared(sm_);
    int arow = wm + (lane & 15);
    uint32_t rA = smb + arow * (ST * 4) + ((lane & 16) ? 16 : 0);
    int brow = wn + (lane & 7) + ((lane & 16) ? 8 : 0);
    uint32_t rB = smb + 6144 * 4 + brow * (ST * 4) + ((lane & 8) ? 16 : 0);
    const uint32_t BUFB = 1536 * 4;
    const uint32_t LOFF = 3072 * 4;

    auto stage = [&](int buf, uint4 ah, uint4 al, uint4 bh, uint4 bl) {
        int o = buf * 1536 + am * ST + sw;
        *(uint4*)&AsH[o] = ah;
        *(uint4*)&AsL[o] = al;
        *(uint4*)&BsH[o] = bh;
        *(uint4*)&BsL[o] = bl;
    };

    uint4 ah = *(const uint4*)&g_hh[(size_t)(me0 + am) * 128 + sw];
    uint4 al = *(const uint4*)&g_hl[(size_t)(me0 + am) * 128 + sw];
    uint4 bh = *(const uint4*)&g_w2h[am * 128 + sw];
    uint4 bl = *(const uint4*)&g_w2l[am * 128 + sw];
    stage(0, ah, al, bh, bl);
    __syncthreads();

    float acc[2][8][4];
#pragma unroll
    for (int i = 0; i < 2; i++)
#pragma unroll
        for (int j = 0; j < 8; j++)
#pragma unroll
            for (int k = 0; k < 4; k++) acc[i][j][k] = 0.f;

    const int KT = NH / 16;  // 16
    for (int kt = 0; kt < KT; ++kt) {
        int cur = kt & 1;
        if (kt < KT - 1) {
            int o = (kt + 1) * 8 + sw;
            ah = *(const uint4*)&g_hh[(size_t)(me0 + am) * 128 + o];
            al = *(const uint4*)&g_hl[(size_t)(me0 + am) * 128 + o];
            bh = *(const uint4*)&g_w2h[am * 128 + o];
            bl = *(const uint4*)&g_w2l[am * 128 + o];
        }
        uint32_t aH[2][4], aL[2][4];
#pragma unroll
        for (int mf = 0; mf < 2; mf++) {
            uint32_t ad = rA + cur * BUFB + mf * (16 * ST * 4);
            ldsm4(aH[mf], ad);
            ldsm4(aL[mf], ad + LOFF);
        }
#pragma unroll
        for (int j = 0; j < 4; j++) {
            uint32_t bH[4], bL[4];
            uint32_t bd = rB + cur * BUFB + j * (16 * ST * 4);
            ldsm4(bH, bd);
            ldsm4(bL, bd + LOFF);
#pragma unroll
            for (int mf = 0; mf < 2; mf++) {
                mma16(acc[mf][2 * j],     aH[mf], bH[0], bH[1]);
                mma16(acc[mf][2 * j],     aH[mf], bL[0], bL[1]);
                mma16(acc[mf][2 * j],     aL[mf], bH[0], bH[1]);
                mma16(acc[mf][2 * j + 1], aH[mf], bH[2], bH[3]);
                mma16(acc[mf][2 * j + 1], aH[mf], bL[2], bL[3]);
                mma16(acc[mf][2 * j + 1], aL[mf], bH[2], bH[3]);
            }
        }
        if (kt < KT - 1) stage(cur ^ 1, ah, al, bh, bl);
        __syncthreads();
    }

#pragma unroll
    for (int mf = 0; mf < 2; mf++) {
        int m = me0 + wm + mf * 16 + grp;
#pragma unroll
        for (int nf = 0; nf < 8; nf++) {
            int h = wn + nf * 8 + quad * 2;
            float bb0 = b2[h], bb1 = b2[h + 1];
            float2 v0, v1;
            v0.x = acc[mf][nf][0] + bb0;
            v0.y = acc[mf][nf][1] + bb1;
            v1.x = acc[mf][nf][2] + bb0;
            v1.y = acc[mf][nf][3] + bb1;
            *(float2*)&g_cand[(size_t)m * 128 + h] = v0;
            *(float2*)&g_cand[(size_t)(m + 8) * 128 + h] = v1;
        }
    }
}

// ---------------- gate + edge_feat + readout logits + segment max ----------------
__global__ void k_gate(const float* __restrict__ hef, const float* __restrict__ attr,
                       const int* __restrict__ ei, const int* __restrict__ batch,
                       const float* __restrict__ Wupd, const float* __restrict__ bupd,
                       const float* __restrict__ Wread, const float* __restrict__ bread,
                       float* __restrict__ out) {
    int warp = threadIdx.x >> 5, lane = threadIdx.x & 31;
    int e = blockIdx.x * 8 + warp;
    if (e >= NE) return;
    int r = ei[e], c = ei[NE + e];
    float4 cd = ((const float4*)g_cand)[e * 32 + lane];
    float4 hh = ((const float4*)hef)[e * 32 + lane];
    float4 wuc = *(const float4*)&Wupd[400 + lane * 4];
    float4 wuh = *(const float4*)&Wupd[272 + lane * 4];
    float p = dot4(cd, wuc) + dot4(hh, wuh);
    float4 a4 = make_float4(0.f, 0.f, 0.f, 0.f);
    if (lane < 4) {
        a4 = ((const float4*)attr)[e * 4 + lane];
        float4 wua = *(const float4*)&Wupd[256 + lane * 4];
        p += dot4(a4, wua);
    }
    p = wred(p);
    float gv = p + g_nproj[r * 8 + 2] + g_nproj[c * 8 + 3] + bupd[0];
    float g = 1.f / (1.f + expf(-gv));
    float4 ef;
    ef.x = fmaf(g, cd.x - hh.x, hh.x);
    ef.y = fmaf(g, cd.y - hh.y, hh.y);
    ef.z = fmaf(g, cd.z - hh.z, hh.z);
    ef.w = fmaf(g, cd.w - hh.w, hh.w);
    ((float4*)out)[e * 32 + lane] = ef;

    float4 wre = *(const float4*)&Wread[256 + lane * 4];
    float q = dot4(ef, wre);
    if (lane < 4) {
        float4 wra = *(const float4*)&Wread[384 + lane * 4];
        q += dot4(a4, wra);
    }
    q = wred(q);
    if (lane == 0) {
        float rl = q + g_nproj[r * 8 + 4] + g_nproj[c * 8 + 5] + bread[0];
        g_rlogit[e] = rl;
        atomicMaxF(&g_gmax[batch[r]], rl);
    }
}

// ---------------- readout exp + segment sum ----------------
__global__ void k_rexp(const int* __restrict__ ei, const int* __restrict__ batch) {
    __shared__ float ss[NG];
    int t = threadIdx.x;
    if (t < NG) ss[t] = 0.f;
    __syncthreads();
    int e = blockIdx.x * 256 + t;
    if (e < NE) {
        int gi = batch[ei[e]];
        float rw = expf(g_rlogit[e] - g_gmax[gi]);
        g_rw[e] = rw;
        atomicAdd(&ss[gi], rw);
    }
    __syncthreads();
    if (t < NG && ss[t] != 0.f) atomicAdd(&g_gsum[t], ss[t]);
}

// ---------------- readout scatter ----------------
__global__ void k_rscatter(const int* __restrict__ ei, const int* __restrict__ batch,
                           const float* __restrict__ out) {
    __shared__ float sacc[NG * DE];
    int t = threadIdx.x;
    for (int i = t; i < NG * DE; i += 256) sacc[i] = 0.f;
    __syncthreads();
    int warp = t >> 5, lane = t & 31;
    for (int e = blockIdx.x * 8 + warp; e < NE; e += gridDim.x * 8) {
        int gi = batch[ei[e]];
        float rn = g_rw[e] / (g_gsum[gi] + 1e-16f);
        float4 ef = ((const float4*)out)[e * 32 + lane];
        float* p = &sacc[gi * 128 + lane * 4];
        atomicAdd(p + 0, rn * ef.x);
        atomicAdd(p + 1, rn * ef.y);
        atomicAdd(p + 2, rn * ef.z);
        atomicAdd(p + 3, rn * ef.w);
    }
    __syncthreads();
    for (int i = t; i < NG * DE; i += 256)
        if (sacc[i] != 0.f) atomicAdd(&g_graphfeat[i], sacc[i]);
}

// ---------------- confidence ----------------
__global__ void k_conf(const float* __restrict__ Wscore, const float* __restrict__ bscore,
                       float* __restrict__ out) {
    int g = blockIdx.x, t = threadIdx.x;
    float v = g_graphfeat[g * 128 + t] * Wscore[t];
    v = wred(v);
    __shared__ float sm[4];
    if ((t & 31) == 0) sm[t >> 5] = v;
    __syncthreads();
    if (t == 0) {
        float s = sm[0] + sm[1] + sm[2] + sm[3] + bscore[0];
        out[(size_t)NE * DE + g] = 1.f / (1.f + expf(-s));
    }
}

// ---------------- launch ----------------
extern "C" void kernel_launch(void* const* d_in, const int* in_sizes, int n_in,
                              void* d_out, int out_size) {
    const float* x      = (const float*)d_in[0];
    const float* hef    = (const float*)d_in[1];
    const float* attr   = (const float*)d_in[2];
    const int*   ei     = (const int*)d_in[3];
    const int*   batch  = (const int*)d_in[4];
    const float* Wagg   = (const float*)d_in[6];
    const float* bagg   = (const float*)d_in[7];
    const float* W1     = (const float*)d_in[8];
    const float* b1     = (const float*)d_in[9];
    const float* W2     = (const float*)d_in[10];
    const float* b2     = (const float*)d_in[11];
    const float* Wupd   = (const float*)d_in[12];
    const float* bupd   = (const float*)d_in[13];
    const float* Wread  = (const float*)d_in[14];
    const float* bread  = (const float*)d_in[15];
    const float* Wscore = (const float*)d_in[16];
    const float* bscore = (const float*)d_in[17];
    float* out = (float*)d_out;

    static bool attr_set = false;
    if (!attr_set) {
        cudaFuncSetAttribute(k_gemm1, cudaFuncAttributeMaxDynamicSharedMemorySize, G1_WORDS * 4);
        cudaFuncSetAttribute(k_gemm2, cudaFuncAttributeMaxDynamicSharedMemorySize, G2_WORDS * 4);
        attr_set = true;
    }

    k_init<<<(NN * DE + 255) / 256, 256>>>();
    k_wsplit<<<(256 * 264 + 255) / 256, 256>>>(W1, W2);
    k_nodeproj<<<(NN + 7) / 8, 256>>>(x, Wagg, Wupd, Wread);
    k_agglogit<<<NE / 8, 256>>>(hef, attr, ei, Wagg, bagg);
    k_expw<<<NE / 256, 256>>>(ei);
    k_nscatter<<<NE / 8, 256>>>(hef, ei);
    k_gemm1<<<dim3(NE / 128, 2), 256, G1_WORDS * 4>>>(x, attr, ei, b1);
    k_gemm2<<<NE / 128, 256, G2_WORDS * 4>>>(b2);
    k_gate<<<NE / 8, 256>>>(hef, attr, ei, batch, Wupd, bupd, Wread, bread, out);
    k_rexp<<<NE / 256, 256>>>(ei, batch);
    k_rscatter<<<296, 256>>>(ei, batch, out);
    k_conf<<<NG, 128>>>(Wscore, bscore, out);
}

// round 6
// speedup vs baseline: 1.2506x; 1.0219x over previous
#include <cuda_runtime.h>
#include <cuda_bf16.h>
#include <stdint.h>

#define NN 20000
#define NE 320000
#define DN 128
#define DE 128
#define DA 16
#define NH 256
#define NG 64
#define K1TOT 528
#define ST 12              // smem row stride in u32 words (8 used + 4 pad)

// ---------------- scratch ----------------
__device__ float g_nproj[NN * 8];
__device__ float g_eproj[NE * 2];     // attr-dot for upd, read
__device__ float g_logit[NE];
__device__ float g_nmax[NN];
__device__ float g_nsum[NN];
__device__ float g_nodefeat[NN * DE];
__device__ uint32_t g_w1h[256 * 264], g_w1l[256 * 264];   // W1 split, [n][kpair]
__device__ uint32_t g_w2h[128 * 128], g_w2l[128 * 128];   // W2 split, [n][kpair]
__device__ uint32_t g_hh[40960000], g_hl[40960000];       // hidden packed [m][kpair]
__device__ float g_rlogit[NE];
__device__ float g_rw[NE];
__device__ float g_gmax[NG];
__device__ float g_gsum[NG];
__device__ float g_graphfeat[NG * DE];

// ---------------- helpers ----------------
__device__ __forceinline__ float dot4(float4 a, float4 b) {
    return fmaf(a.x, b.x, fmaf(a.y, b.y, fmaf(a.z, b.z, a.w * b.w)));
}

__device__ __forceinline__ float wred(float v) {
    v += __shfl_xor_sync(0xffffffffu, v, 16);
    v += __shfl_xor_sync(0xffffffffu, v, 8);
    v += __shfl_xor_sync(0xffffffffu, v, 4);
    v += __shfl_xor_sync(0xffffffffu, v, 2);
    v += __shfl_xor_sync(0xffffffffu, v, 1);
    return v;
}

__device__ __forceinline__ void atomicMaxF(float* addr, float v) {
    int* ia = (int*)addr;
    int old = __float_as_int(*addr);
    while (__int_as_float(old) < v) {
        int prev = atomicCAS(ia, old, __float_as_int(v));
        if (prev == old) break;
        old = prev;
    }
}

__device__ __forceinline__ uint32_t packhi(float f0, float f1) {
    __nv_bfloat162 h = __floats2bfloat162_rn(f0, f1);
    return *(uint32_t*)&h;
}
__device__ __forceinline__ uint32_t packlo(float f0, float f1, uint32_t hi) {
    __nv_bfloat162 h = *(__nv_bfloat162*)&hi;
    float l0 = f0 - __bfloat162float(h.x);
    float l1 = f1 - __bfloat162float(h.y);
    __nv_bfloat162 l = __floats2bfloat162_rn(l0, l1);
    return *(uint32_t*)&l;
}

__device__ __forceinline__ void mma16(float* c, const uint32_t* a, uint32_t b0, uint32_t b1) {
    asm volatile("mma.sync.aligned.m16n8k16.row.col.f32.bf16.bf16.f32 "
        "{%0,%1,%2,%3}, {%4,%5,%6,%7}, {%8,%9}, {%0,%1,%2,%3};"
        : "+f"(c[0]), "+f"(c[1]), "+f"(c[2]), "+f"(c[3])
        : "r"(a[0]), "r"(a[1]), "r"(a[2]), "r"(a[3]), "r"(b0), "r"(b1));
}

__device__ __forceinline__ void ldsm4(uint32_t* r, uint32_t addr) {
    asm volatile("ldmatrix.sync.aligned.m8n8.x4.shared.b16 {%0,%1,%2,%3}, [%4];"
        : "=r"(r[0]), "=r"(r[1]), "=r"(r[2]), "=r"(r[3]) : "r"(addr));
}

// ---------------- init ----------------
__global__ void k_init() {
    int i = blockIdx.x * 256 + threadIdx.x;
    if (i < NN * DE) g_nodefeat[i] = 0.f;
    if (i < NN) { g_nmax[i] = -1e30f; g_nsum[i] = 0.f; }
    if (i < NG * DE) g_graphfeat[i] = 0.f;
    if (i < NG) { g_gmax[i] = -1e30f; g_gsum[i] = 0.f; }
}

// ---------------- one-time weight bf16 hi/lo split (transposed [n][kp]) ----------------
__global__ void k_wsplit(const float* __restrict__ W1, const float* __restrict__ W2) {
    int i = blockIdx.x * 256 + threadIdx.x;
    if (i < 256 * 264) {
        int n = i / 264, kp = i % 264;
        float f0 = W1[(2 * kp) * 256 + n], f1 = W1[(2 * kp + 1) * 256 + n];
        uint32_t h = packhi(f0, f1);
        g_w1h[i] = h; g_w1l[i] = packlo(f0, f1, h);
    }
    if (i < 128 * 128) {
        int n = i >> 7, kp = i & 127;
        float f0 = W2[(2 * kp) * 128 + n], f1 = W2[(2 * kp + 1) * 128 + n];
        uint32_t h = packhi(f0, f1);
        g_w2h[i] = h; g_w2l[i] = packlo(f0, f1, h);
    }
}

// ---------------- per-node scalar projections ----------------
__global__ void k_nodeproj(const float* __restrict__ x, const float* __restrict__ Wagg,
                           const float* __restrict__ Wupd, const float* __restrict__ Wread) {
    int warp = threadIdx.x >> 5, lane = threadIdx.x & 31;
    int n = blockIdx.x * 8 + warp;
    if (n >= NN) return;
    float4 xv = ((const float4*)x)[n * 32 + lane];
    const float4* wa = (const float4*)Wagg;
    const float4* wu = (const float4*)Wupd;
    const float4* wr = (const float4*)Wread;
    float s0 = dot4(xv, wa[lane]);
    float s1 = dot4(xv, wa[32 + lane]);
    float s2 = dot4(xv, wu[lane]);
    float s3 = dot4(xv, wu[32 + lane]);
    float s4 = dot4(xv, wr[lane]);
    float s5 = dot4(xv, wr[32 + lane]);
    s0 = wred(s0); s1 = wred(s1); s2 = wred(s2);
    s3 = wred(s3); s4 = wred(s4); s5 = wred(s5);
    if (lane == 0) {
        g_nproj[n * 8 + 0] = s0; g_nproj[n * 8 + 1] = s1;
        g_nproj[n * 8 + 2] = s2; g_nproj[n * 8 + 3] = s3;
        g_nproj[n * 8 + 4] = s4; g_nproj[n * 8 + 5] = s5;
    }
}

// ---------------- agg logits + segment max + attr projections ----------------
__global__ void k_agglogit(const float* __restrict__ hef, const float* __restrict__ attr,
                           const int* __restrict__ ei, const float* __restrict__ Wagg,
                           const float* __restrict__ bagg, const float* __restrict__ Wupd,
                           const float* __restrict__ Wread) {
    int warp = threadIdx.x >> 5, lane = threadIdx.x & 31;
    int e = blockIdx.x * 8 + warp;
    if (e >= NE) return;
    int r = ei[e], c = ei[NE + e];
    float4 h4 = ((const float4*)hef)[e * 32 + lane];
    float4 wh = *(const float4*)&Wagg[272 + lane * 4];
    float p = dot4(h4, wh);
    float pu = 0.f, pr = 0.f;
    if (lane < 4) {
        float4 a4 = ((const float4*)attr)[e * 4 + lane];
        p += dot4(a4, *(const float4*)&Wagg[256 + lane * 4]);
        pu = dot4(a4, *(const float4*)&Wupd[256 + lane * 4]);
        pr = dot4(a4, *(const float4*)&Wread[384 + lane * 4]);
    }
    p = wred(p); pu = wred(pu); pr = wred(pr);
    if (lane == 0) {
        float logit = p + g_nproj[r * 8 + 0] + g_nproj[c * 8 + 1] + bagg[0];
        g_logit[e] = logit;
        g_eproj[e * 2 + 0] = pu;
        g_eproj[e * 2 + 1] = pr;
        atomicMaxF(&g_nmax[c], logit);
    }
}

// ---------------- exp + unnormalized scatter + segment sum ----------------
__global__ void k_expscatter(const float* __restrict__ hef, const int* __restrict__ ei) {
    int warp = threadIdx.x >> 5, lane = threadIdx.x & 31;
    int e = blockIdx.x * 8 + warp;
    if (e >= NE) return;
    int c = ei[NE + e];
    float w = expf(g_logit[e] - g_nmax[c]);
    float4 h4 = ((const float4*)hef)[e * 32 + lane];
    float* p = &g_nodefeat[c * 128 + lane * 4];
    asm volatile("red.global.add.v4.f32 [%0], {%1,%2,%3,%4};"
        :: "l"(p), "f"(w * h4.x), "f"(w * h4.y), "f"(w * h4.z), "f"(w * h4.w)
        : "memory");
    if (lane == 0) atomicAdd(&g_nsum[c], w);
}

// ---------------- normalize node_feat ----------------
__global__ void k_nnorm() {
    int i = blockIdx.x * 256 + threadIdx.x;
    if (i >= NN * DE) return;
    int n = i >> 7;
    g_nodefeat[i] = g_nodefeat[i] / (g_nsum[n] + 1e-16f);
}

// ==================== GEMM1 (ldmatrix + pre-split B): hidden packed out ====================
#define G1_WORDS 12544

__global__ void __launch_bounds__(256, 2)
k_gemm1(const float* __restrict__ x, const float* __restrict__ attr,
        const int* __restrict__ ei, const float* __restrict__ b1) {
    extern __shared__ uint32_t sm_[];
    uint32_t* AsH = sm_;
    uint32_t* AsL = sm_ + 3072;
    uint32_t* BsH = sm_ + 6144;
    uint32_t* BsL = sm_ + 9216;
    int* srol = (int*)(sm_ + 12288);
    int* scol = srol + 128;

    int t = threadIdx.x;
    int me0 = blockIdx.x * 128, hn0 = blockIdx.y * 128;
    if (t < 128) srol[t] = ei[me0 + t];
    else scol[t - 128] = ei[NE + me0 + t - 128];
    __syncthreads();

    int am = t >> 1, ak = (t & 1) * 8, sw = (t & 1) * 4;
    int lane = t & 31, w = t >> 5;
    int wm = (w & 3) * 32, wn = (w >> 2) * 64;
    int grp = lane >> 2, quad = lane & 3;

    uint32_t smb = (uint32_t)__cvta_generic_to_shared(sm_);
    int arow = wm + (lane & 15);
    uint32_t rA = smb + arow * (ST * 4) + ((lane & 16) ? 16 : 0);
    int brow = wn + (lane & 7) + ((lane & 16) ? 8 : 0);
    uint32_t rB = smb + 6144 * 4 + brow * (ST * 4) + ((lane & 8) ? 16 : 0);
    const uint32_t BUFB = 1536 * 4;
    const uint32_t LOFF = 3072 * 4;

    auto ldA = [&](int k) -> float4 {
        if (k < 128) return *(const float4*)&x[srol[am] * 128 + k];
        if (k < 256) return *(const float4*)&g_nodefeat[srol[am] * 128 + (k - 128)];
        if (k < 384) return *(const float4*)&x[scol[am] * 128 + (k - 256)];
        if (k < 512) return *(const float4*)&g_nodefeat[scol[am] * 128 + (k - 384)];
        return *(const float4*)&attr[(me0 + am) * 16 + (k - 512)];
    };

    auto stage = [&](int buf, float4 a0, float4 a1, uint4 bh, uint4 bl) {
        float fa[8] = {a0.x, a0.y, a0.z, a0.w, a1.x, a1.y, a1.z, a1.w};
        uint4 h4, l4;
#pragma unroll
        for (int i = 0; i < 4; i++) {
            uint32_t h = packhi(fa[2 * i], fa[2 * i + 1]);
            ((uint32_t*)&h4)[i] = h;
            ((uint32_t*)&l4)[i] = packlo(fa[2 * i], fa[2 * i + 1], h);
        }
        int o = buf * 1536 + am * ST + sw;
        *(uint4*)&AsH[o] = h4;
        *(uint4*)&AsL[o] = l4;
        *(uint4*)&BsH[o] = bh;
        *(uint4*)&BsL[o] = bl;
    };

    float4 a0 = ldA(ak), a1 = ldA(ak + 4);
    uint4 bh = *(const uint4*)&g_w1h[(size_t)(hn0 + am) * 264 + sw];
    uint4 bl = *(const uint4*)&g_w1l[(size_t)(hn0 + am) * 264 + sw];
    stage(0, a0, a1, bh, bl);
    __syncthreads();

    float acc[2][8][4];
#pragma unroll
    for (int i = 0; i < 2; i++)
#pragma unroll
        for (int j = 0; j < 8; j++)
#pragma unroll
            for (int k = 0; k < 4; k++) acc[i][j][k] = 0.f;

    const int KT = K1TOT / 16;  // 33
    for (int kt = 0; kt < KT; ++kt) {
        int cur = kt & 1;
        if (kt < KT - 1) {
            int k0 = (kt + 1) * 16;
            a0 = ldA(k0 + ak); a1 = ldA(k0 + ak + 4);
            bh = *(const uint4*)&g_w1h[(size_t)(hn0 + am) * 264 + (kt + 1) * 8 + sw];
            bl = *(const uint4*)&g_w1l[(size_t)(hn0 + am) * 264 + (kt + 1) * 8 + sw];
        }
        uint32_t aH[2][4], aL[2][4];
#pragma unroll
        for (int mf = 0; mf < 2; mf++) {
            uint32_t ad = rA + cur * BUFB + mf * (16 * ST * 4);
            ldsm4(aH[mf], ad);
            ldsm4(aL[mf], ad + LOFF);
        }
#pragma unroll
        for (int j = 0; j < 4; j++) {
            uint32_t bH[4], bL[4];
            uint32_t bd = rB + cur * BUFB + j * (16 * ST * 4);
            ldsm4(bH, bd);
            ldsm4(bL, bd + LOFF);
#pragma unroll
            for (int mf = 0; mf < 2; mf++) {
                mma16(acc[mf][2 * j],     aH[mf], bH[0], bH[1]);
                mma16(acc[mf][2 * j],     aH[mf], bL[0], bL[1]);
                mma16(acc[mf][2 * j],     aL[mf], bH[0], bH[1]);
                mma16(acc[mf][2 * j + 1], aH[mf], bH[2], bH[3]);
                mma16(acc[mf][2 * j + 1], aH[mf], bL[2], bL[3]);
                mma16(acc[mf][2 * j + 1], aL[mf], bH[2], bH[3]);
            }
        }
        if (kt < KT - 1) stage(cur ^ 1, a0, a1, bh, bl);
        __syncthreads();
    }

#pragma unroll
    for (int mf = 0; mf < 2; mf++) {
        int m = me0 + wm + mf * 16 + grp;
#pragma unroll
        for (int nf = 0; nf < 8; nf++) {
            int c0 = hn0 + wn + nf * 8 + quad * 2;
            float bb0 = b1[c0], bb1 = b1[c0 + 1];
            int kp = c0 >> 1;
            float v0 = fmaxf(acc[mf][nf][0] + bb0, 0.f);
            float v1 = fmaxf(acc[mf][nf][1] + bb1, 0.f);
            uint32_t h = packhi(v0, v1);
            g_hh[(size_t)m * 128 + kp] = h;
            g_hl[(size_t)m * 128 + kp] = packlo(v0, v1, h);
            float v2 = fmaxf(acc[mf][nf][2] + bb0, 0.f);
            float v3 = fmaxf(acc[mf][nf][3] + bb1, 0.f);
            h = packhi(v2, v3);
            g_hh[(size_t)(m + 8) * 128 + kp] = h;
            g_hl[(size_t)(m + 8) * 128 + kp] = packlo(v2, v3, h);
        }
    }
}

// ==================== GEMM2 fused: cand -> gate -> ef(out) -> readout logit ====================
// smem: mainloop 12288 words + srol@12288, scol@12416, sred@12544(256f), sg@12800(128f)
#define G2_WORDS 12928

__global__ void __launch_bounds__(256, 2)
k_gemm2f(const float* __restrict__ hef, const int* __restrict__ ei,
         const int* __restrict__ batch, const float* __restrict__ b2,
         const float* __restrict__ Wupd, const float* __restrict__ bupd,
         const float* __restrict__ Wread, const float* __restrict__ bread,
         float* __restrict__ out) {
    extern __shared__ uint32_t sm_[];
    uint32_t* AsH = sm_;
    uint32_t* AsL = sm_ + 3072;
    uint32_t* BsH = sm_ + 6144;
    uint32_t* BsL = sm_ + 9216;
    int*   srol = (int*)(sm_ + 12288);
    int*   scol = (int*)(sm_ + 12416);
    float* sred = (float*)(sm_ + 12544);
    float* sg   = (float*)(sm_ + 12800);

    int t = threadIdx.x;
    int me0 = blockIdx.x * 128;
    if (t < 128) srol[t] = ei[me0 + t];
    else scol[t - 128] = ei[NE + me0 + t - 128];

    int am = t >> 1, sw = (t & 1) * 4;
    int lane = t & 31, w = t >> 5;
    int wm = (w & 3) * 32, wn = (w >> 2) * 64;
    int grp = lane >> 2, quad = lane & 3;

    uint32_t smb = (uint32_t)__cvta_generic_to_shared(sm_);
    int arow = wm + (lane & 15);
    uint32_t rA = smb + arow * (ST * 4) + ((lane & 16) ? 16 : 0);
    int brow = wn + (lane & 7) + ((lane & 16) ? 8 : 0);
    uint32_t rB = smb + 6144 * 4 + brow * (ST * 4) + ((lane & 8) ? 16 : 0);
    const uint32_t BUFB = 1536 * 4;
    const uint32_t LOFF = 3072 * 4;

    auto stage = [&](int buf, uint4 ah, uint4 al, uint4 bh, uint4 bl) {
        int o = buf * 1536 + am * ST + sw;
        *(uint4*)&AsH[o] = ah;
        *(uint4*)&AsL[o] = al;
        *(uint4*)&BsH[o] = bh;
        *(uint4*)&BsL[o] = bl;
    };

    uint4 ah = *(const uint4*)&g_hh[(size_t)(me0 + am) * 128 + sw];
    uint4 al = *(const uint4*)&g_hl[(size_t)(me0 + am) * 128 + sw];
    uint4 bh = *(const uint4*)&g_w2h[am * 128 + sw];
    uint4 bl = *(const uint4*)&g_w2l[am * 128 + sw];
    stage(0, ah, al, bh, bl);
    __syncthreads();

    float acc[2][8][4];
#pragma unroll
    for (int i = 0; i < 2; i++)
#pragma unroll
        for (int j = 0; j < 8; j++)
#pragma unroll
            for (int k = 0; k < 4; k++) acc[i][j][k] = 0.f;

    const int KT = NH / 16;  // 16
    for (int kt = 0; kt < KT; ++kt) {
        int cur = kt & 1;
        if (kt < KT - 1) {
            int o = (kt + 1) * 8 + sw;
            ah = *(const uint4*)&g_hh[(size_t)(me0 + am) * 128 + o];
            al = *(const uint4*)&g_hl[(size_t)(me0 + am) * 128 + o];
            bh = *(const uint4*)&g_w2h[am * 128 + o];
            bl = *(const uint4*)&g_w2l[am * 128 + o];
        }
        uint32_t aH[2][4], aL[2][4];
#pragma unroll
        for (int mf = 0; mf < 2; mf++) {
            uint32_t ad = rA + cur * BUFB + mf * (16 * ST * 4);
            ldsm4(aH[mf], ad);
            ldsm4(aL[mf], ad + LOFF);
        }
#pragma unroll
        for (int j = 0; j < 4; j++) {
            uint32_t bH[4], bL[4];
            uint32_t bd = rB + cur * BUFB + j * (16 * ST * 4);
            ldsm4(bH, bd);
            ldsm4(bL, bd + LOFF);
#pragma unroll
            for (int mf = 0; mf < 2; mf++) {
                mma16(acc[mf][2 * j],     aH[mf], bH[0], bH[1]);
                mma16(acc[mf][2 * j],     aH[mf], bL[0], bL[1]);
                mma16(acc[mf][2 * j],     aL[mf], bH[0], bH[1]);
                mma16(acc[mf][2 * j + 1], aH[mf], bH[2], bH[3]);
                mma16(acc[mf][2 * j + 1], aH[mf], bL[2], bL[3]);
                mma16(acc[mf][2 * j + 1], aL[mf], bH[2], bH[3]);
            }
        }
        if (kt < KT - 1) stage(cur ^ 1, ah, al, bh, bl);
        __syncthreads();
    }

    // acc += b2 -> cand
#pragma unroll
    for (int mf = 0; mf < 2; mf++)
#pragma unroll
        for (int nf = 0; nf < 8; nf++) {
            int c0 = wn + nf * 8 + quad * 2;
            float bb0 = b2[c0], bb1 = b2[c0 + 1];
            acc[mf][nf][0] += bb0; acc[mf][nf][1] += bb1;
            acc[mf][nf][2] += bb0; acc[mf][nf][3] += bb1;
        }

    // ---- epilogue pass 1: gate logit dot ----
    float s0 = 0.f, s1 = 0.f, s2 = 0.f, s3 = 0.f;
#pragma unroll
    for (int mf = 0; mf < 2; mf++) {
        int r0 = wm + mf * 16 + grp;
#pragma unroll
        for (int nf = 0; nf < 8; nf++) {
            int c = wn + nf * 8 + quad * 2;
            float2 wc = *(const float2*)&Wupd[400 + c];
            float2 whv = *(const float2*)&Wupd[272 + c];
            float2 h0 = *(const float2*)&hef[(size_t)(me0 + r0) * 128 + c];
            float2 h1 = *(const float2*)&hef[(size_t)(me0 + r0 + 8) * 128 + c];
            float p0 = acc[mf][nf][0] * wc.x + acc[mf][nf][1] * wc.y + h0.x * whv.x + h0.y * whv.y;
            float p1 = acc[mf][nf][2] * wc.x + acc[mf][nf][3] * wc.y + h1.x * whv.x + h1.y * whv.y;
            if (mf == 0) { s0 += p0; s1 += p1; } else { s2 += p0; s3 += p1; }
        }
    }
    s0 += __shfl_xor_sync(0xffffffffu, s0, 1); s0 += __shfl_xor_sync(0xffffffffu, s0, 2);
    s1 += __shfl_xor_sync(0xffffffffu, s1, 1); s1 += __shfl_xor_sync(0xffffffffu, s1, 2);
    s2 += __shfl_xor_sync(0xffffffffu, s2, 1); s2 += __shfl_xor_sync(0xffffffffu, s2, 2);
    s3 += __shfl_xor_sync(0xffffffffu, s3, 1); s3 += __shfl_xor_sync(0xffffffffu, s3, 2);
    if (quad == 0) {
        int nh = w >> 2;
        sred[(wm + grp) * 2 + nh] = s0;
        sred[(wm + 8 + grp) * 2 + nh] = s1;
        sred[(wm + 16 + grp) * 2 + nh] = s2;
        sred[(wm + 24 + grp) * 2 + nh] = s3;
    }
    __syncthreads();
    if (t < 128) {
        int e = me0 + t, r = srol[t], c = scol[t];
        float tot = sred[t * 2] + sred[t * 2 + 1];
        float gv = tot + g_eproj[e * 2] + g_nproj[r * 8 + 2] + g_nproj[c * 8 + 3] + bupd[0];
        sg[t] = 1.f / (1.f + expf(-gv));
    }
    __syncthreads();

    // ---- epilogue pass 2: ef = g*cand + (1-g)*hef, write out, readout dot ----
    s0 = s1 = s2 = s3 = 0.f;
#pragma unroll
    for (int mf = 0; mf < 2; mf++) {
        int r0 = wm + mf * 16 + grp;
        float g0 = sg[r0], g1 = sg[r0 + 8];
#pragma unroll
        for (int nf = 0; nf < 8; nf++) {
            int c = wn + nf * 8 + quad * 2;
            float2 h0 = *(const float2*)&hef[(size_t)(me0 + r0) * 128 + c];
            float2 h1 = *(const float2*)&hef[(size_t)(me0 + r0 + 8) * 128 + c];
            float2 e0, e1;
            e0.x = fmaf(g0, acc[mf][nf][0] - h0.x, h0.x);
            e0.y = fmaf(g0, acc[mf][nf][1] - h0.y, h0.y);
            e1.x = fmaf(g1, acc[mf][nf][2] - h1.x, h1.x);
            e1.y = fmaf(g1, acc[mf][nf][3] - h1.y, h1.y);
            *(float2*)&out[(size_t)(me0 + r0) * 128 + c] = e0;
            *(float2*)&out[(size_t)(me0 + r0 + 8) * 128 + c] = e1;
            float2 wr = *(const float2*)&Wread[256 + c];
            float p0 = e0.x * wr.x + e0.y * wr.y;
            float p1 = e1.x * wr.x + e1.y * wr.y;
            if (mf == 0) { s0 += p0; s1 += p1; } else { s2 += p0; s3 += p1; }
        }
    }
    s0 += __shfl_xor_sync(0xffffffffu, s0, 1); s0 += __shfl_xor_sync(0xffffffffu, s0, 2);
    s1 += __shfl_xor_sync(0xffffffffu, s1, 1); s1 += __shfl_xor_sync(0xffffffffu, s1, 2);
    s2 += __shfl_xor_sync(0xffffffffu, s2, 1); s2 += __shfl_xor_sync(0xffffffffu, s2, 2);
    s3 += __shfl_xor_sync(0xffffffffu, s3, 1); s3 += __shfl_xor_sync(0xffffffffu, s3, 2);
    if (quad == 0) {
        int nh = w >> 2;
        sred[(wm + grp) * 2 + nh] = s0;
        sred[(wm + 8 + grp) * 2 + nh] = s1;
        sred[(wm + 16 + grp) * 2 + nh] = s2;
        sred[(wm + 24 + grp) * 2 + nh] = s3;
    }
    __syncthreads();
    if (t < 128) {
        int e = me0 + t, r = srol[t], c = scol[t];
        float tot = sred[t * 2] + sred[t * 2 + 1];
        float rl = tot + g_eproj[e * 2 + 1] + g_nproj[r * 8 + 4] + g_nproj[c * 8 + 5] + bread[0];
        g_rlogit[e] = rl;
        atomicMaxF(&g_gmax[batch[r]], rl);
    }
}

// ---------------- readout exp + segment sum ----------------
__global__ void k_rexp(const int* __restrict__ ei, const int* __restrict__ batch) {
    __shared__ float ss[NG];
    int t = threadIdx.x;
    if (t < NG) ss[t] = 0.f;
    __syncthreads();
    int e = blockIdx.x * 256 + t;
    if (e < NE) {
        int gi = batch[ei[e]];
        float rw = expf(g_rlogit[e] - g_gmax[gi]);
        g_rw[e] = rw;
        atomicAdd(&ss[gi], rw);
    }
    __syncthreads();
    if (t < NG && ss[t] != 0.f) atomicAdd(&g_gsum[t], ss[t]);
}

// ---------------- readout scatter ----------------
__global__ void k_rscatter(const int* __restrict__ ei, const int* __restrict__ batch,
                           const float* __restrict__ out) {
    __shared__ float sacc[NG * DE];
    int t = threadIdx.x;
    for (int i = t; i < NG * DE; i += 256) sacc[i] = 0.f;
    __syncthreads();
    int warp = t >> 5, lane = t & 31;
    for (int e = blockIdx.x * 8 + warp; e < NE; e += gridDim.x * 8) {
        int gi = batch[ei[e]];
        float rn = g_rw[e] / (g_gsum[gi] + 1e-16f);
        float4 ef = ((const float4*)out)[e * 32 + lane];
        float* p = &sacc[gi * 128 + lane * 4];
        atomicAdd(p + 0, rn * ef.x);
        atomicAdd(p + 1, rn * ef.y);
        atomicAdd(p + 2, rn * ef.z);
        atomicAdd(p + 3, rn * ef.w);
    }
    __syncthreads();
    for (int i = t; i < NG * DE; i += 256)
        if (sacc[i] != 0.f) atomicAdd(&g_graphfeat[i], sacc[i]);
}

// ---------------- confidence ----------------
__global__ void k_conf(const float* __restrict__ Wscore, const float* __restrict__ bscore,
                       float* __restrict__ out) {
    int g = blockIdx.x, t = threadIdx.x;
    float v = g_graphfeat[g * 128 + t] * Wscore[t];
    v = wred(v);
    __shared__ float sm[4];
    if ((t & 31) == 0) sm[t >> 5] = v;
    __syncthreads();
    if (t == 0) {
        float s = sm[0] + sm[1] + sm[2] + sm[3] + bscore[0];
        out[(size_t)NE * DE + g] = 1.f / (1.f + expf(-s));
    }
}

// ---------------- launch ----------------
extern "C" void kernel_launch(void* const* d_in, const int* in_sizes, int n_in,
                              void* d_out, int out_size) {
    const float* x      = (const float*)d_in[0];
    const float* hef    = (const float*)d_in[1];
    const float* attr   = (const float*)d_in[2];
    const int*   ei     = (const int*)d_in[3];
    const int*   batch  = (const int*)d_in[4];
    const float* Wagg   = (const float*)d_in[6];
    const float* bagg   = (const float*)d_in[7];
    const float* W1     = (const float*)d_in[8];
    const float* b1     = (const float*)d_in[9];
    const float* W2     = (const float*)d_in[10];
    const float* b2     = (const float*)d_in[11];
    const float* Wupd   = (const float*)d_in[12];
    const float* bupd   = (const float*)d_in[13];
    const float* Wread  = (const float*)d_in[14];
    const float* bread  = (const float*)d_in[15];
    const float* Wscore = (const float*)d_in[16];
    const float* bscore = (const float*)d_in[17];
    float* out = (float*)d_out;

    static bool attr_set = false;
    if (!attr_set) {
        cudaFuncSetAttribute(k_gemm1, cudaFuncAttributeMaxDynamicSharedMemorySize, G1_WORDS * 4);
        cudaFuncSetAttribute(k_gemm2f, cudaFuncAttributeMaxDynamicSharedMemorySize, G2_WORDS * 4);
        attr_set = true;
    }

    k_init<<<(NN * DE + 255) / 256, 256>>>();
    k_wsplit<<<(256 * 264 + 255) / 256, 256>>>(W1, W2);
    k_nodeproj<<<(NN + 7) / 8, 256>>>(x, Wagg, Wupd, Wread);
    k_agglogit<<<NE / 8, 256>>>(hef, attr, ei, Wagg, bagg, Wupd, Wread);
    k_expscatter<<<NE / 8, 256>>>(hef, ei);
    k_nnorm<<<(NN * DE + 255) / 256, 256>>>();
    k_gemm1<<<dim3(NE / 128, 2), 256, G1_WORDS * 4>>>(x, attr, ei, b1);
    k_gemm2f<<<NE / 128, 256, G2_WORDS * 4>>>(hef, ei, batch, b2, Wupd, bupd,
                                              Wread, bread, out);
    k_rexp<<<NE / 256, 256>>>(ei, batch);
    k_rscatter<<<296, 256>>>(ei, batch, out);
    k_conf<<<NG, 128>>>(Wscore, bscore, out);
}